// round 1
// baseline (speedup 1.0000x reference)
#include <cuda_runtime.h>
#include <math.h>

#define OBS_LEN 20
#define BATCH   2048
#define IN_DIM  512
#define HID     1024
#define G4      4096   // 4*HID

#define BM  128   // batch rows per block
#define BN  32    // hidden units per block (x4 gates = 128 cols)
#define BK  16
#define PAD 132   // 128 + 4 (float4-aligned, kills store bank conflicts across kq)

// Scratch (static device globals — no allocation allowed in kernel_launch)
__device__ float g_h0buf[BATCH * HID];
__device__ float g_h1buf[BATCH * HID];
__device__ float g_cbuf [BATCH * HID];
__device__ float g_Wc[G4 * 2];
__device__ float g_bc[G4];

// ---------------------------------------------------------------------------
// Prep: fold the input embedding into the LSTM input weights.
//   Wc[j][i] = sum_h W_ih[j,h] * W_emb[h,i]   (i in {0,1})
//   bc[j]    = sum_h W_ih[j,h] * b_emb[h] + b_ih[j] + b_hh[j]
// One warp per j (4096 warps).
// ---------------------------------------------------------------------------
__global__ void prep_kernel(const float* __restrict__ W_emb,
                            const float* __restrict__ b_emb,
                            const float* __restrict__ W_ih,
                            const float* __restrict__ b_ih,
                            const float* __restrict__ b_hh) {
    int warp = (blockIdx.x * blockDim.x + threadIdx.x) >> 5;
    int lane = threadIdx.x & 31;
    if (warp >= G4) return;
    const float* wrow = W_ih + (size_t)warp * IN_DIM;
    float s0 = 0.f, s1 = 0.f, sb = 0.f;
    for (int h = lane; h < IN_DIM; h += 32) {
        float w = wrow[h];
        s0 += w * W_emb[h * 2 + 0];
        s1 += w * W_emb[h * 2 + 1];
        sb += w * b_emb[h];
    }
#pragma unroll
    for (int o = 16; o > 0; o >>= 1) {
        s0 += __shfl_down_sync(0xffffffffu, s0, o);
        s1 += __shfl_down_sync(0xffffffffu, s1, o);
        sb += __shfl_down_sync(0xffffffffu, sb, o);
    }
    if (lane == 0) {
        g_Wc[warp * 2 + 0] = s0;
        g_Wc[warp * 2 + 1] = s1;
        g_bc[warp] = sb + b_ih[warp] + b_hh[warp];
    }
}

__device__ __forceinline__ float sigm(float x) { return 1.f / (1.f + expf(-x)); }

// ---------------------------------------------------------------------------
// One LSTM timestep, fully fused:
//   gates[b, g*H + n] = sum_k hin[b,k]*W_hh[g*H+n, k]
//                     + obs0*Wc[.,0] + obs1*Wc[.,1] + bc[.]
//   c = sig(f)*c + sig(i)*tanh(g);  hout = sig(o)*tanh(c)
//
// Block tile: 128 batch x 128 cols. Column c of the tile corresponds to
//   j_global = (c & 3)*HID + n0 + (c >> 2)    (gate-minor interleave)
// so each thread's 8-col microtile = 2 hidden units x all 4 gates, and the
// cell update happens entirely in registers.
// ---------------------------------------------------------------------------
__global__ __launch_bounds__(256, 2) void lstm_step_kernel(
    const float* __restrict__ hin,
    const float* __restrict__ W_hh,
    const float* __restrict__ obs_t,   // [BATCH, 2] for this timestep
    float* __restrict__ hout) {
    __shared__ float As[BK][PAD];  // [k][batch_row]
    __shared__ float Bs[BK][PAD];  // [k][col]

    const int tid = threadIdx.x;
    const int tx = tid & 15;   // col group: cols tx*8 .. tx*8+7
    const int ty = tid >> 4;   // row group: rows ty*8 .. ty*8+7
    const int bRow = blockIdx.x * BM;
    const int n0   = blockIdx.y * BN;

    float acc[8][8];
#pragma unroll
    for (int i = 0; i < 8; i++)
#pragma unroll
        for (int j = 0; j < 8; j++) acc[i][j] = 0.f;

    for (int k0 = 0; k0 < HID; k0 += BK) {
        // Cooperative load: 512 float4 slots (2 per thread) for each of A, B.
#pragma unroll
        for (int q = 0; q < 2; q++) {
            int s  = tid * 2 + q;
            int r  = s >> 2;           // 0..127  (batch row / tile col)
            int kq = (s & 3) << 2;     // 0,4,8,12

            float4 va = *(const float4*)(hin + (size_t)(bRow + r) * HID + k0 + kq);
            As[kq + 0][r] = va.x; As[kq + 1][r] = va.y;
            As[kq + 2][r] = va.z; As[kq + 3][r] = va.w;

            int jg = ((r & 3) << 10) + n0 + (r >> 2);  // gate*HID + hidden
            float4 vb = *(const float4*)(W_hh + (size_t)jg * HID + k0 + kq);
            Bs[kq + 0][r] = vb.x; Bs[kq + 1][r] = vb.y;
            Bs[kq + 2][r] = vb.z; Bs[kq + 3][r] = vb.w;
        }
        __syncthreads();

#pragma unroll
        for (int k = 0; k < BK; k++) {
            float a[8], b[8];
            *(float4*)(a)     = *(const float4*)&As[k][ty * 8];
            *(float4*)(a + 4) = *(const float4*)&As[k][ty * 8 + 4];
            *(float4*)(b)     = *(const float4*)&Bs[k][tx * 8];
            *(float4*)(b + 4) = *(const float4*)&Bs[k][tx * 8 + 4];
#pragma unroll
            for (int i = 0; i < 8; i++)
#pragma unroll
                for (int j = 0; j < 8; j++)
                    acc[i][j] += a[i] * b[j];
        }
        __syncthreads();
    }

    // Epilogue: per thread, 8 batch rows x 2 hidden units (all 4 gates in regs).
#pragma unroll
    for (int i = 0; i < 8; i++) {
        int b = bRow + ty * 8 + i;
        float o0 = obs_t[b * 2 + 0];
        float o1 = obs_t[b * 2 + 1];
#pragma unroll
        for (int m = 0; m < 2; m++) {
            int n = n0 + tx * 2 + m;
            float gv[4];
#pragma unroll
            for (int g = 0; g < 4; g++) {
                int jg = g * HID + n;
                gv[g] = acc[i][m * 4 + g]
                      + o0 * g_Wc[jg * 2 + 0]
                      + o1 * g_Wc[jg * 2 + 1]
                      + g_bc[jg];
            }
            float ig = sigm(gv[0]);
            float fg = sigm(gv[1]);
            float gg = tanhf(gv[2]);
            float og = sigm(gv[3]);
            size_t idx = (size_t)b * HID + n;
            float cn = fg * g_cbuf[idx] + ig * gg;
            g_cbuf[idx] = cn;
            hout[idx] = og * tanhf(cn);
        }
    }
}

// ---------------------------------------------------------------------------
extern "C" void kernel_launch(void* const* d_in, const int* in_sizes, int n_in,
                              void* d_out, int out_size) {
    const float* obs   = (const float*)d_in[0];
    const float* h0    = (const float*)d_in[1];
    const float* c0    = (const float*)d_in[2];
    const float* W_emb = (const float*)d_in[3];
    const float* b_emb = (const float*)d_in[4];
    const float* W_ih  = (const float*)d_in[5];
    const float* W_hh  = (const float*)d_in[6];
    const float* b_ih  = (const float*)d_in[7];
    const float* b_hh  = (const float*)d_in[8];

    float *hbuf0, *hbuf1, *cbuf;
    cudaGetSymbolAddress((void**)&hbuf0, g_h0buf);
    cudaGetSymbolAddress((void**)&hbuf1, g_h1buf);
    cudaGetSymbolAddress((void**)&cbuf,  g_cbuf);

    cudaMemcpyAsync(hbuf0, h0, sizeof(float) * BATCH * HID,
                    cudaMemcpyDeviceToDevice, 0);
    cudaMemcpyAsync(cbuf, c0, sizeof(float) * BATCH * HID,
                    cudaMemcpyDeviceToDevice, 0);

    prep_kernel<<<512, 256>>>(W_emb, b_emb, W_ih, b_ih, b_hh);

    dim3 grid(BATCH / BM, HID / BN);  // (16, 32)
    float* bufs[2] = {hbuf0, hbuf1};
    for (int t = 0; t < OBS_LEN; t++) {
        const float* hin = bufs[t & 1];
        float* hout = (t == OBS_LEN - 1) ? (float*)d_out : bufs[(t + 1) & 1];
        lstm_step_kernel<<<grid, 256>>>(hin, W_hh,
                                        obs + (size_t)t * BATCH * 2, hout);
    }
}

// round 2
// speedup vs baseline: 1.0005x; 1.0005x over previous
#include <cuda_runtime.h>
#include <math.h>

#define OBS_LEN 20
#define BATCH   2048
#define IN_DIM  512
#define HID     1024
#define G4      4096   // 4*HID

#define BM  128   // batch rows per block
#define BN  32    // hidden units per block (x4 gates = 128 cols)
#define BK  16
#define PAD 132   // 128 + 4 (float4-aligned, kills store bank conflicts across kq)

// Scratch (static device globals — no allocation allowed in kernel_launch)
__device__ float g_h0buf[BATCH * HID];
__device__ float g_h1buf[BATCH * HID];
__device__ float g_cbuf [BATCH * HID];
__device__ float g_Wc[G4 * 2];
__device__ float g_bc[G4];

// ---------------------------------------------------------------------------
// Prep: fold the input embedding into the LSTM input weights.
//   Wc[j][i] = sum_h W_ih[j,h] * W_emb[h,i]   (i in {0,1})
//   bc[j]    = sum_h W_ih[j,h] * b_emb[h] + b_ih[j] + b_hh[j]
// One warp per j (4096 warps).
// ---------------------------------------------------------------------------
__global__ void prep_kernel(const float* __restrict__ W_emb,
                            const float* __restrict__ b_emb,
                            const float* __restrict__ W_ih,
                            const float* __restrict__ b_ih,
                            const float* __restrict__ b_hh) {
    int warp = (blockIdx.x * blockDim.x + threadIdx.x) >> 5;
    int lane = threadIdx.x & 31;
    if (warp >= G4) return;
    const float* wrow = W_ih + (size_t)warp * IN_DIM;
    float s0 = 0.f, s1 = 0.f, sb = 0.f;
    for (int h = lane; h < IN_DIM; h += 32) {
        float w = wrow[h];
        s0 += w * W_emb[h * 2 + 0];
        s1 += w * W_emb[h * 2 + 1];
        sb += w * b_emb[h];
    }
#pragma unroll
    for (int o = 16; o > 0; o >>= 1) {
        s0 += __shfl_down_sync(0xffffffffu, s0, o);
        s1 += __shfl_down_sync(0xffffffffu, s1, o);
        sb += __shfl_down_sync(0xffffffffu, sb, o);
    }
    if (lane == 0) {
        g_Wc[warp * 2 + 0] = s0;
        g_Wc[warp * 2 + 1] = s1;
        g_bc[warp] = sb + b_ih[warp] + b_hh[warp];
    }
}

__device__ __forceinline__ float sigm(float x) { return 1.f / (1.f + expf(-x)); }

// ---------------------------------------------------------------------------
// One LSTM timestep, fully fused:
//   gates[b, g*H + n] = sum_k hin[b,k]*W_hh[g*H+n, k]
//                     + obs0*Wc[.,0] + obs1*Wc[.,1] + bc[.]
//   c = sig(f)*c + sig(i)*tanh(g);  hout = sig(o)*tanh(c)
//
// Block tile: 128 batch x 128 cols. Column c of the tile corresponds to
//   j_global = (c & 3)*HID + n0 + (c >> 2)    (gate-minor interleave)
// so each thread's 8-col microtile = 2 hidden units x all 4 gates, and the
// cell update happens entirely in registers.
// ---------------------------------------------------------------------------
__global__ __launch_bounds__(256, 2) void lstm_step_kernel(
    const float* __restrict__ hin,
    const float* __restrict__ W_hh,
    const float* __restrict__ obs_t,   // [BATCH, 2] for this timestep
    float* __restrict__ hout) {
    __shared__ float As[BK][PAD];  // [k][batch_row]
    __shared__ float Bs[BK][PAD];  // [k][col]

    const int tid = threadIdx.x;
    const int tx = tid & 15;   // col group: cols tx*8 .. tx*8+7
    const int ty = tid >> 4;   // row group: rows ty*8 .. ty*8+7
    const int bRow = blockIdx.x * BM;
    const int n0   = blockIdx.y * BN;

    float acc[8][8];
#pragma unroll
    for (int i = 0; i < 8; i++)
#pragma unroll
        for (int j = 0; j < 8; j++) acc[i][j] = 0.f;

    for (int k0 = 0; k0 < HID; k0 += BK) {
        // Cooperative load: 512 float4 slots (2 per thread) for each of A, B.
#pragma unroll
        for (int q = 0; q < 2; q++) {
            int s  = tid * 2 + q;
            int r  = s >> 2;           // 0..127  (batch row / tile col)
            int kq = (s & 3) << 2;     // 0,4,8,12

            float4 va = *(const float4*)(hin + (size_t)(bRow + r) * HID + k0 + kq);
            As[kq + 0][r] = va.x; As[kq + 1][r] = va.y;
            As[kq + 2][r] = va.z; As[kq + 3][r] = va.w;

            int jg = ((r & 3) << 10) + n0 + (r >> 2);  // gate*HID + hidden
            float4 vb = *(const float4*)(W_hh + (size_t)jg * HID + k0 + kq);
            Bs[kq + 0][r] = vb.x; Bs[kq + 1][r] = vb.y;
            Bs[kq + 2][r] = vb.z; Bs[kq + 3][r] = vb.w;
        }
        __syncthreads();

#pragma unroll
        for (int k = 0; k < BK; k++) {
            float a[8], b[8];
            *(float4*)(a)     = *(const float4*)&As[k][ty * 8];
            *(float4*)(a + 4) = *(const float4*)&As[k][ty * 8 + 4];
            *(float4*)(b)     = *(const float4*)&Bs[k][tx * 8];
            *(float4*)(b + 4) = *(const float4*)&Bs[k][tx * 8 + 4];
#pragma unroll
            for (int i = 0; i < 8; i++)
#pragma unroll
                for (int j = 0; j < 8; j++)
                    acc[i][j] += a[i] * b[j];
        }
        __syncthreads();
    }

    // Epilogue: per thread, 8 batch rows x 2 hidden units (all 4 gates in regs).
#pragma unroll
    for (int i = 0; i < 8; i++) {
        int b = bRow + ty * 8 + i;
        float o0 = obs_t[b * 2 + 0];
        float o1 = obs_t[b * 2 + 1];
#pragma unroll
        for (int m = 0; m < 2; m++) {
            int n = n0 + tx * 2 + m;
            float gv[4];
#pragma unroll
            for (int g = 0; g < 4; g++) {
                int jg = g * HID + n;
                gv[g] = acc[i][m * 4 + g]
                      + o0 * g_Wc[jg * 2 + 0]
                      + o1 * g_Wc[jg * 2 + 1]
                      + g_bc[jg];
            }
            float ig = sigm(gv[0]);
            float fg = sigm(gv[1]);
            float gg = tanhf(gv[2]);
            float og = sigm(gv[3]);
            size_t idx = (size_t)b * HID + n;
            float cn = fg * g_cbuf[idx] + ig * gg;
            g_cbuf[idx] = cn;
            hout[idx] = og * tanhf(cn);
        }
    }
}

// ---------------------------------------------------------------------------
extern "C" void kernel_launch(void* const* d_in, const int* in_sizes, int n_in,
                              void* d_out, int out_size) {
    const float* obs   = (const float*)d_in[0];
    const float* h0    = (const float*)d_in[1];
    const float* c0    = (const float*)d_in[2];
    const float* W_emb = (const float*)d_in[3];
    const float* b_emb = (const float*)d_in[4];
    const float* W_ih  = (const float*)d_in[5];
    const float* W_hh  = (const float*)d_in[6];
    const float* b_ih  = (const float*)d_in[7];
    const float* b_hh  = (const float*)d_in[8];

    float *hbuf0, *hbuf1, *cbuf;
    cudaGetSymbolAddress((void**)&hbuf0, g_h0buf);
    cudaGetSymbolAddress((void**)&hbuf1, g_h1buf);
    cudaGetSymbolAddress((void**)&cbuf,  g_cbuf);

    cudaMemcpyAsync(hbuf0, h0, sizeof(float) * BATCH * HID,
                    cudaMemcpyDeviceToDevice, 0);
    cudaMemcpyAsync(cbuf, c0, sizeof(float) * BATCH * HID,
                    cudaMemcpyDeviceToDevice, 0);

    prep_kernel<<<512, 256>>>(W_emb, b_emb, W_ih, b_ih, b_hh);

    dim3 grid(BATCH / BM, HID / BN);  // (16, 32)
    float* bufs[2] = {hbuf0, hbuf1};
    for (int t = 0; t < OBS_LEN; t++) {
        const float* hin = bufs[t & 1];
        float* hout = (t == OBS_LEN - 1) ? (float*)d_out : bufs[(t + 1) & 1];
        lstm_step_kernel<<<grid, 256>>>(hin, W_hh,
                                        obs + (size_t)t * BATCH * 2, hout);
    }
}

// round 4
// speedup vs baseline: 2.4507x; 2.4494x over previous
#include <cuda_runtime.h>
#include <cuda_bf16.h>
#include <math.h>
#include <stdint.h>

#define OBS_LEN 20
#define BATCH   2048
#define IN_DIM  512
#define HID     1024
#define G4      4096
#define K3      3072          // 3*HID split-K concat
#define CHUNK   32            // K per pipeline chunk
#define NCHUNK  96            // K3/CHUNK
#define TILE_M  128
#define TILE_N  128
#define ROWB    80            // smem row stride bytes (64 data + 16 pad)
#define STAGE_BYTES (256 * ROWB)      // 128 A rows + 128 B rows = 20480
#define NSTAGE  4
#define SMEM_DYN (NSTAGE * STAGE_BYTES)   // 81920

// ---------------------------------------------------------------------------
// Device scratch
// ---------------------------------------------------------------------------
__device__ __align__(16) float          g_Wc[G4 * 2];
__device__ __align__(16) float          g_bc[G4];
__device__ __align__(16) __nv_bfloat16  g_Wperm[(size_t)G4 * K3];  // 25 MB
__device__ __align__(16) __nv_bfloat16  g_A0[(size_t)BATCH * K3];  // 12.6 MB
__device__ __align__(16) __nv_bfloat16  g_A1[(size_t)BATCH * K3];
__device__ __align__(16) float          g_cbuf[(size_t)BATCH * HID];

// ---------------------------------------------------------------------------
// Helpers (family-portable PTX only: cp.async / ldmatrix / mma.sync)
// ---------------------------------------------------------------------------
__device__ __forceinline__ uint32_t smem_u32(const void* p) {
    uint32_t a;
    asm("{ .reg .u64 t; cvta.to.shared.u64 t, %1; cvt.u32.u64 %0, t; }"
        : "=r"(a) : "l"(p));
    return a;
}
__device__ __forceinline__ void cp16(uint32_t dst, const void* src) {
    asm volatile("cp.async.cg.shared.global [%0], [%1], 16;"
                 :: "r"(dst), "l"(src) : "memory");
}
__device__ __forceinline__ void ldsm4(uint32_t* r, uint32_t addr) {
    asm volatile("ldmatrix.sync.aligned.m8n8.x4.shared.b16 {%0,%1,%2,%3}, [%4];"
                 : "=r"(r[0]), "=r"(r[1]), "=r"(r[2]), "=r"(r[3]) : "r"(addr));
}
__device__ __forceinline__ void mma16816(float* d, const uint32_t* a,
                                         uint32_t b0, uint32_t b1) {
    asm volatile(
        "mma.sync.aligned.m16n8k16.row.col.f32.bf16.bf16.f32 "
        "{%0,%1,%2,%3},{%4,%5,%6,%7},{%8,%9},{%0,%1,%2,%3};"
        : "+f"(d[0]), "+f"(d[1]), "+f"(d[2]), "+f"(d[3])
        : "r"(a[0]), "r"(a[1]), "r"(a[2]), "r"(a[3]), "r"(b0), "r"(b1));
}
__device__ __forceinline__ float sigm(float x) {
    return __fdividef(1.f, 1.f + __expf(-x));
}
__device__ __forceinline__ float tanh_f(float x) {
    return __fdividef(2.f, 1.f + __expf(-2.f * x)) - 1.f;
}

// ---------------------------------------------------------------------------
// Prep 1: fold embedding into per-gate input weights (Wc [G4][2], bc [G4]).
// ---------------------------------------------------------------------------
__global__ void prep_wc_kernel(const float* __restrict__ W_emb,
                               const float* __restrict__ b_emb,
                               const float* __restrict__ W_ih,
                               const float* __restrict__ b_ih,
                               const float* __restrict__ b_hh) {
    int warp = (blockIdx.x * blockDim.x + threadIdx.x) >> 5;
    int lane = threadIdx.x & 31;
    if (warp >= G4) return;
    const float* wrow = W_ih + (size_t)warp * IN_DIM;
    float s0 = 0.f, s1 = 0.f, sb = 0.f;
    for (int h = lane; h < IN_DIM; h += 32) {
        float w = wrow[h];
        s0 += w * W_emb[h * 2 + 0];
        s1 += w * W_emb[h * 2 + 1];
        sb += w * b_emb[h];
    }
#pragma unroll
    for (int o = 16; o > 0; o >>= 1) {
        s0 += __shfl_down_sync(0xffffffffu, s0, o);
        s1 += __shfl_down_sync(0xffffffffu, s1, o);
        sb += __shfl_down_sync(0xffffffffu, sb, o);
    }
    if (lane == 0) {
        g_Wc[warp * 2 + 0] = s0;
        g_Wc[warp * 2 + 1] = s1;
        g_bc[warp] = sb + b_ih[warp] + b_hh[warp];
    }
}

// ---------------------------------------------------------------------------
// Prep 2: permuted bf16-split B' = [W_hi | W_lo | W_hi].
// Row permutation matches the mma d-fragment layout:
//   pr = y*128 + c ;  warpN=c>>5, cl=c&31
//   gate = cl>>3 ; unit = y*32 + warpN*8 + (cl&7) ; j = gate*1024 + unit
// so thread lane-quad q in warp holds units {2q,2q+1} with gate = n8-tile idx.
// ---------------------------------------------------------------------------
__global__ void prep_wperm_kernel(const float* __restrict__ W_hh) {
    int pr = blockIdx.x;
    int y = pr >> 7, c = pr & 127;
    int warpN = c >> 5, cl = c & 31;
    int gate = cl >> 3;
    int u = (y << 5) + (warpN << 3) + (cl & 7);
    int j = (gate << 10) + u;
    const float* wrow = W_hh + (size_t)j * HID;
    __nv_bfloat16* orow = g_Wperm + (size_t)pr * K3;
    for (int kk = threadIdx.x * 4; kk < K3; kk += blockDim.x * 4) {
        int seg = kk >> 10;
        int ksrc = kk - (seg << 10);
        float4 w = *(const float4*)(wrow + ksrc);
        float v[4] = {w.x, w.y, w.z, w.w};
        union { __nv_bfloat16 b[4]; uint2 u2; } out;
#pragma unroll
        for (int t = 0; t < 4; t++) {
            __nv_bfloat16 hi = __float2bfloat16(v[t]);
            if (seg == 1) out.b[t] = __float2bfloat16(v[t] - __bfloat162float(hi));
            else          out.b[t] = hi;
        }
        *(uint2*)(orow + kk) = out.u2;
    }
}

// ---------------------------------------------------------------------------
// Prep 3: h0 -> A'(step 0) = [hi | hi | lo]
// ---------------------------------------------------------------------------
__global__ void init_h0_kernel(const float* __restrict__ h0) {
    int v = blockIdx.x * blockDim.x + threadIdx.x;
    int e = v * 4;
    int b = e >> 10, k = e & 1023;
    float4 h = *(const float4*)(h0 + e);
    float vv[4] = {h.x, h.y, h.z, h.w};
    union { __nv_bfloat16 b[4]; uint2 u2; } phi, plo;
#pragma unroll
    for (int t = 0; t < 4; t++) {
        __nv_bfloat16 hi = __float2bfloat16(vv[t]);
        phi.b[t] = hi;
        plo.b[t] = __float2bfloat16(vv[t] - __bfloat162float(hi));
    }
    __nv_bfloat16* row = g_A0 + (size_t)b * K3;
    *(uint2*)(row + k)        = phi.u2;
    *(uint2*)(row + 1024 + k) = phi.u2;
    *(uint2*)(row + 2048 + k) = plo.u2;
}

// ---------------------------------------------------------------------------
// Fused LSTM step: 128x128 HMMA GEMM over K'=3072 + in-register cell update.
// ---------------------------------------------------------------------------
__global__ __launch_bounds__(256, 2) void lstm_step_kernel(
    const __nv_bfloat16* __restrict__ Acur,
    __nv_bfloat16* __restrict__ Anext,
    const float* __restrict__ obs_t,
    float* __restrict__ hout) {
    extern __shared__ __align__(128) char dyn[];
    const int tid = threadIdx.x;
    const int wid = tid >> 5, lane = tid & 31;
    const int warpM = wid >> 2, warpN = wid & 3;   // 2 x 4 warp grid
    const int bRow = blockIdx.x * TILE_M;
    const int prBase = blockIdx.y * TILE_N;

    const uint32_t base = smem_u32(dyn);

    // ldmatrix per-thread address components
    const int g = lane >> 3, jj = lane & 7;
    // A matrix tile: rows (g&1)*8 + j, k-half = g>>1
    const uint32_t aoff = (uint32_t)((warpM * 64 + ((g & 1) << 3) + jj) * ROWB
                                     + ((g >> 1) << 4));
    // B matrix tile: rows (g>>1)*8 + j, k-half = g&1  (B rows start at 128*ROWB)
    const uint32_t boff = (uint32_t)((128 + warpN * 32 + ((g >> 1) << 3) + jj) * ROWB
                                     + ((g & 1) << 4));

    float acc[4][4][4];
#pragma unroll
    for (int m = 0; m < 4; m++)
#pragma unroll
        for (int n = 0; n < 4; n++)
#pragma unroll
            for (int x = 0; x < 4; x++) acc[m][n][x] = 0.f;

    // loader per-thread mapping: 2x16B for A row lr, 2x16B for B row lr
    const int lr = tid >> 1;
    const int lc = (tid & 1) * 2;
    const __nv_bfloat16* asrc = Acur + (size_t)(bRow + lr) * K3 + lc * 8;
    const __nv_bfloat16* bsrc = g_Wperm + (size_t)(prBase + lr) * K3 + lc * 8;
    const uint32_t adst = base + lr * ROWB + lc * 16;
    const uint32_t bdst = base + 128 * ROWB + lr * ROWB + lc * 16;

    // Prologue: fill stages 0..2
#pragma unroll
    for (int s = 0; s < NSTAGE - 1; s++) {
        uint32_t so = s * STAGE_BYTES;
        int k0 = s * CHUNK;
        cp16(adst + so, asrc + k0); cp16(adst + so + 16, asrc + k0 + 8);
        cp16(bdst + so, bsrc + k0); cp16(bdst + so + 16, bsrc + k0 + 8);
        asm volatile("cp.async.commit_group;" ::: "memory");
    }

#pragma unroll 4
    for (int it = 0; it < NCHUNK; ++it) {
        asm volatile("cp.async.wait_group 2;" ::: "memory");
        __syncthreads();
        uint32_t so = (uint32_t)(it & (NSTAGE - 1)) * STAGE_BYTES;

#pragma unroll
        for (int kt = 0; kt < 2; kt++) {
            uint32_t aA = base + so + aoff + kt * 32;
            uint32_t aB = base + so + boff + kt * 32;
            uint32_t aF[4][4], bF[8];
#pragma unroll
            for (int m = 0; m < 4; m++) ldsm4(aF[m], aA + m * 16 * ROWB);
            ldsm4(bF,     aB);
            ldsm4(bF + 4, aB + 16 * ROWB);
#pragma unroll
            for (int m = 0; m < 4; m++)
#pragma unroll
                for (int n = 0; n < 4; n++) {
                    int np = n >> 1, sub = n & 1;
                    mma16816(acc[m][n], aF[m],
                             bF[np * 4 + sub * 2], bF[np * 4 + sub * 2 + 1]);
                }
        }

        int nl = it + NSTAGE - 1;
        if (nl < NCHUNK) {
            uint32_t so2 = (uint32_t)(nl & (NSTAGE - 1)) * STAGE_BYTES;
            int k0 = nl * CHUNK;
            cp16(adst + so2, asrc + k0); cp16(adst + so2 + 16, asrc + k0 + 8);
            cp16(bdst + so2, bsrc + k0); cp16(bdst + so2 + 16, bsrc + k0 + 8);
        }
        asm volatile("cp.async.commit_group;" ::: "memory");
    }

    // ------------------ fused LSTM epilogue (all in registers) ------------------
    const int q = lane & 3;
    const int u0 = blockIdx.y * 32 + warpN * 8 + 2 * q;    // 2 units: u0, u0+1
    const int rbase = bRow + warpM * 64 + (lane >> 2);

    float wcx[2][4], wcy[2][4], bcv[2][4];
#pragma unroll
    for (int i = 0; i < 2; i++)
#pragma unroll
        for (int gg = 0; gg < 4; gg++) {
            int j = (gg << 10) + u0 + i;
            float2 w = *(const float2*)(g_Wc + j * 2);
            wcx[i][gg] = w.x; wcy[i][gg] = w.y; bcv[i][gg] = g_bc[j];
        }

#pragma unroll
    for (int m = 0; m < 4; m++)
#pragma unroll
        for (int s = 0; s < 2; s++) {
            int b = rbase + m * 16 + s * 8;
            float2 ob = *(const float2*)(obs_t + b * 2);
            float* crow = g_cbuf + (size_t)b * HID;
            float2 cold = *(const float2*)(crow + u0);
            float cprev[2] = {cold.x, cold.y};
            float cn[2], hn[2];
#pragma unroll
            for (int i = 0; i < 2; i++) {
                float gv[4];
#pragma unroll
                for (int gg = 0; gg < 4; gg++)
                    gv[gg] = acc[m][gg][s * 2 + i]
                           + ob.x * wcx[i][gg] + ob.y * wcy[i][gg] + bcv[i][gg];
                float ig = sigm(gv[0]);
                float fg = sigm(gv[1]);
                float gc = tanh_f(gv[2]);
                float og = sigm(gv[3]);
                cn[i] = fg * cprev[i] + ig * gc;
                hn[i] = og * tanh_f(cn[i]);
            }
            *(float2*)(crow + u0) = make_float2(cn[0], cn[1]);
            if (hout)
                *(float2*)(hout + (size_t)b * HID + u0) = make_float2(hn[0], hn[1]);

            union { __nv_bfloat16 h[2]; uint32_t u; } phi, plo;
#pragma unroll
            for (int i = 0; i < 2; i++) {
                __nv_bfloat16 hi = __float2bfloat16(hn[i]);
                phi.h[i] = hi;
                plo.h[i] = __float2bfloat16(hn[i] - __bfloat162float(hi));
            }
            __nv_bfloat16* ar = Anext + (size_t)b * K3 + u0;
            *(uint32_t*)(ar)        = phi.u;
            *(uint32_t*)(ar + 1024) = phi.u;
            *(uint32_t*)(ar + 2048) = plo.u;
        }
}

// ---------------------------------------------------------------------------
extern "C" void kernel_launch(void* const* d_in, const int* in_sizes, int n_in,
                              void* d_out, int out_size) {
    const float* obs   = (const float*)d_in[0];
    const float* h0    = (const float*)d_in[1];
    const float* c0    = (const float*)d_in[2];
    const float* W_emb = (const float*)d_in[3];
    const float* b_emb = (const float*)d_in[4];
    const float* W_ih  = (const float*)d_in[5];
    const float* W_hh  = (const float*)d_in[6];
    const float* b_ih  = (const float*)d_in[7];
    const float* b_hh  = (const float*)d_in[8];

    float* cbuf;
    __nv_bfloat16 *a0, *a1;
    cudaGetSymbolAddress((void**)&cbuf, g_cbuf);
    cudaGetSymbolAddress((void**)&a0, g_A0);
    cudaGetSymbolAddress((void**)&a1, g_A1);

    cudaMemcpyAsync(cbuf, c0, sizeof(float) * BATCH * HID,
                    cudaMemcpyDeviceToDevice, 0);

    prep_wc_kernel<<<512, 256>>>(W_emb, b_emb, W_ih, b_ih, b_hh);
    prep_wperm_kernel<<<G4, 256>>>(W_hh);
    init_h0_kernel<<<BATCH * HID / 4 / 256, 256>>>(h0);

    cudaFuncSetAttribute(lstm_step_kernel,
                         cudaFuncAttributeMaxDynamicSharedMemorySize, SMEM_DYN);

    dim3 grid(BATCH / TILE_M, G4 / TILE_N);   // (16, 32)
    __nv_bfloat16* bufs[2] = {a0, a1};
    for (int t = 0; t < OBS_LEN; t++) {
        lstm_step_kernel<<<grid, 256, SMEM_DYN>>>(
            bufs[t & 1], bufs[(t + 1) & 1],
            obs + (size_t)t * BATCH * 2,
            (t == OBS_LEN - 1) ? (float*)d_out : nullptr);
    }
}